// round 1
// baseline (speedup 1.0000x reference)
#include <cuda_runtime.h>

#define NLAYERS 7
#define EPS_F 1e-5f

// Shapes (fixed by the benchmark's setup_inputs):
//   bsz=8, C=8, QL=KL=128, A=8, cross_range=2
// pw:  [64, 1024, 1024] f32     out: same
// conv_w: [7,8,8,1,3]  conv_b: [7,8]  prelu_a: [7]

__global__ __launch_bounds__(256, 1)
void sag_fused(const float* __restrict__ pw,
               const float* __restrict__ conv_w,
               const float* __restrict__ conv_b,
               const float* __restrict__ prelu_a,
               float* __restrict__ out)
{
    __shared__ float sW[NLAYERS][8][8][3];       // conv weights
    __shared__ float sB[NLAYERS][8];             // bias
    __shared__ float sA[NLAYERS];                // prelu alpha
    __shared__ float sX [32][8][9];              // original x   [slab=p*8+h][c][w] (pad 9)
    __shared__ float sB0[32][8][9];              // ping
    __shared__ float sB1[32][8][9];              // pong
    __shared__ __align__(16) float sRes[4][8][8][8]; // we values [p][h][c][w]
    __shared__ float sPS[4][8][8];               // partial row sums [p][h][c]
    __shared__ float sInv[8][8];                 // 1/(rowsum+eps)   [h][c]

    const int tid = threadIdx.x;
    const int b = blockIdx.x >> 7;       // batch
    const int i = blockIdx.x & 127;      // query index q

    // ---- load conv params to SMEM ----
    for (int t = tid; t < NLAYERS * 8 * 8 * 3; t += 256)
        (&sW[0][0][0][0])[t] = conv_w[t];
    if (tid < NLAYERS * 8) (&sB[0][0])[tid] = conv_b[tid];
    if (tid < NLAYERS)     sA[tid] = prelu_a[tid];

    // thread roles: slab = p*8 + h (32 slabs), co = output channel
    const int slab = tid >> 3;
    const int co   = tid & 7;
    const int pp   = slab >> 3;          // which neighbor pair (0..3)
    const int hh   = slab & 7;           // query-agent row (H dim)
    const int doff = (pp < 2) ? (pp - 2) : (pp - 1);   // {-2,-1,1,2}
    const int j    = i + doff;           // key index k
    const bool pvalid = (j >= 0) && (j < 128);

    // ---- load the x block for (pp, c=co, hh): 8 contiguous floats ----
    {
        float4 v0 = make_float4(0.f, 0.f, 0.f, 0.f), v1 = v0;
        if (pvalid) {
            const float* src = pw +
                ((size_t)((b * 8 + co) * 1024 + (i * 8 + hh)) * 1024 + (size_t)j * 8);
            v0 = *(const float4*)src;
            v1 = *(const float4*)(src + 4);
        }
        float* xd = &sX [slab][co][0];
        float* bd = &sB0[slab][co][0];
        xd[0] = v0.x; xd[1] = v0.y; xd[2] = v0.z; xd[3] = v0.w;
        xd[4] = v1.x; xd[5] = v1.y; xd[6] = v1.z; xd[7] = v1.w;
        bd[0] = v0.x; bd[1] = v0.y; bd[2] = v0.z; bd[3] = v0.w;
        bd[4] = v1.x; bd[5] = v1.y; bd[6] = v1.z; bd[7] = v1.w;
    }
    __syncthreads();

    // ---- 7-layer residual conv stack (1x3 conv along w, channel mixing) ----
    float* cur = &sB0[0][0][0];
    float* nxt = &sB1[0][0][0];
    #pragma unroll 1
    for (int l = 0; l < NLAYERS; l++) {
        float acc[8];
        const float bias = sB[l][co];
        #pragma unroll
        for (int w = 0; w < 8; w++) acc[w] = bias;

        #pragma unroll
        for (int ci = 0; ci < 8; ci++) {
            const float* inr = cur + slab * 72 + ci * 9;
            const float k0 = sW[l][co][ci][0];
            const float k1 = sW[l][co][ci][1];
            const float k2 = sW[l][co][ci][2];
            float r[8];
            #pragma unroll
            for (int w = 0; w < 8; w++) r[w] = inr[w];
            acc[0] += k1 * r[0] + k2 * r[1];
            #pragma unroll
            for (int w = 1; w < 7; w++)
                acc[w] += k0 * r[w - 1] + k1 * r[w] + k2 * r[w + 1];
            acc[7] += k0 * r[6] + k1 * r[7];
        }

        const float pa = sA[l];
        const float* selfr = cur + slab * 72 + co * 9;
        float* outr        = nxt + slab * 72 + co * 9;
        #pragma unroll
        for (int w = 0; w < 8; w++) {
            float y = acc[w];
            y = (y >= 0.f) ? y : pa * y;        // PReLU
            outr[w] = y + selfr[w];             // residual
        }
        __syncthreads();
        float* tmp = cur; cur = nxt; nxt = tmp;
    }
    // result of conv stack is in `cur`; sX still holds original x

    // ---- sparse = relu(x - sigmoid(conv_out)) * (1 - eye); we = expm1(sparse) ----
    {
        const float* xr = &sX[slab][co][0];
        const float* cr = cur + slab * 72 + co * 9;
        float partial = 0.f;
        #pragma unroll
        for (int w = 0; w < 8; w++) {
            float sg = 1.f / (1.f + __expf(-cr[w]));
            float sp = fmaxf(xr[w] - sg, 0.f);
            if (hh == w) sp = 0.f;              // self mask on (a1, a2)
            float we = expm1f(sp);
            if (!pvalid) we = 0.f;
            sRes[pp][hh][co][w] = we;
            partial += we;
        }
        sPS[pp][hh][co] = partial;
    }
    __syncthreads();

    if (tid < 64) {
        const int th = tid >> 3, tc = tid & 7;
        float s = sPS[0][th][tc] + sPS[1][th][tc] + sPS[2][th][tc] + sPS[3][th][tc];
        sInv[th][tc] = 1.f / (s + EPS_F);
    }
    __syncthreads();

    // ---- stream out the 64-row x 4KB output region (mostly zeros) ----
    // row (c,h): out[(b*8+c)*1024 + i*8 + h][:]; each iteration writes one full row.
    const size_t base = ((size_t)(b * 8) * 1024 + (size_t)i * 8) * 1024;
    const int k  = tid >> 1;             // block column index (col4 = tid, 2 float4 per block)
    const int d  = k - i;
    int pi = -1;
    if      (d == -2) pi = 0;
    else if (d == -1) pi = 1;
    else if (d ==  1) pi = 2;
    else if (d ==  2) pi = 3;
    const int w0 = (tid & 1) * 4;

    #pragma unroll 1
    for (int it = 0; it < 64; it++) {
        const int rc = it >> 3;          // c
        const int rh = it & 7;           // h
        float4 v = make_float4(0.f, 0.f, 0.f, 0.f);
        if (pi >= 0) {
            float4 r = *(const float4*)&sRes[pi][rh][rc][w0];
            const float inv = sInv[rh][rc];
            v.x = r.x * inv; v.y = r.y * inv; v.z = r.z * inv; v.w = r.w * inv;
        }
        *(float4*)(out + base + ((size_t)rc * 1024 + rh) * 1024 + (size_t)tid * 4) = v;
    }
}

extern "C" void kernel_launch(void* const* d_in, const int* in_sizes, int n_in,
                              void* d_out, int out_size) {
    const float* pw = (const float*)d_in[0];
    const float* cw = (const float*)d_in[1];
    const float* cb = (const float*)d_in[2];
    const float* pa = (const float*)d_in[3];
    sag_fused<<<1024, 256>>>(pw, cw, cb, pa, (float*)d_out);
}

// round 2
// speedup vs baseline: 1.1063x; 1.1063x over previous
#include <cuda_runtime.h>

#define NLAYERS 7
#define EPS_F 1e-5f

// Shapes (fixed by setup_inputs): bsz=8, C=8, QL=KL=128, A=8, cross_range=2
// pw:  [64, 1024, 1024] f32   out: same
// conv_w: [7,8,8,1,3]  conv_b: [7,8]  prelu_a: [7]
//
// Strategy: d_out is first zero-filled by a memset node (98% of the output is
// exactly zero: expm1(0)=0 and 0/(sum+eps)=0). The compute kernel then handles
// one (b, q) per CTA: the <=4 neighbor A*A blocks per channel go through the
// 7-layer residual conv stack in SMEM, and each thread writes its 8 normalized
// values (contiguous along the last dim) straight from registers.

__global__ __launch_bounds__(256)
void sag_compute(const float* __restrict__ pw,
                 const float* __restrict__ conv_w,
                 const float* __restrict__ conv_b,
                 const float* __restrict__ prelu_a,
                 float* __restrict__ out)
{
    __shared__ float sW[NLAYERS][8][8][3];   // conv weights
    __shared__ float sB[NLAYERS][8];         // bias
    __shared__ float sA[NLAYERS];            // prelu alpha
    __shared__ float sX [32][8][9];          // original x  [slab=p*8+h][c][w] (pad 9)
    __shared__ float sB0[32][8][9];          // ping
    __shared__ float sB1[32][8][9];          // pong
    __shared__ float sPS[4][8][8];           // partial row sums [p][h][c]
    __shared__ float sInv[8][8];             // 1/(rowsum+eps)   [h][c]

    const int tid = threadIdx.x;
    const int b = blockIdx.x >> 7;           // batch
    const int i = blockIdx.x & 127;          // query index q

    // ---- conv params to SMEM ----
    for (int t = tid; t < NLAYERS * 8 * 8 * 3; t += 256)
        (&sW[0][0][0][0])[t] = conv_w[t];
    if (tid < NLAYERS * 8) (&sB[0][0])[tid] = conv_b[tid];
    if (tid < NLAYERS)     sA[tid] = prelu_a[tid];

    // thread roles: slab = p*8 + h (32 slabs), co = channel
    const int slab = tid >> 3;
    const int co   = tid & 7;
    const int pp   = slab >> 3;              // neighbor pair (0..3)
    const int hh   = slab & 7;               // query-agent row
    const int doff = (pp < 2) ? (pp - 2) : (pp - 1);   // {-2,-1,1,2}
    const int j    = i + doff;               // key index k
    const bool pvalid = (j >= 0) && (j < 128);

    // ---- load the x block for (pp, c=co, hh): 8 contiguous floats ----
    {
        float4 v0 = make_float4(0.f, 0.f, 0.f, 0.f), v1 = v0;
        if (pvalid) {
            const float* src = pw +
                ((size_t)((b * 8 + co) * 1024 + (i * 8 + hh)) * 1024 + (size_t)j * 8);
            v0 = *(const float4*)src;
            v1 = *(const float4*)(src + 4);
        }
        float* xd = &sX [slab][co][0];
        float* bd = &sB0[slab][co][0];
        xd[0] = v0.x; xd[1] = v0.y; xd[2] = v0.z; xd[3] = v0.w;
        xd[4] = v1.x; xd[5] = v1.y; xd[6] = v1.z; xd[7] = v1.w;
        bd[0] = v0.x; bd[1] = v0.y; bd[2] = v0.z; bd[3] = v0.w;
        bd[4] = v1.x; bd[5] = v1.y; bd[6] = v1.z; bd[7] = v1.w;
    }
    __syncthreads();

    // ---- 7-layer residual conv stack (1x3 conv along w, full channel mix) ----
    float* cur = &sB0[0][0][0];
    float* nxt = &sB1[0][0][0];
    #pragma unroll 1
    for (int l = 0; l < NLAYERS; l++) {
        float acc[8];
        const float bias = sB[l][co];
        #pragma unroll
        for (int w = 0; w < 8; w++) acc[w] = bias;

        #pragma unroll
        for (int ci = 0; ci < 8; ci++) {
            const float* inr = cur + slab * 72 + ci * 9;
            const float k0 = sW[l][co][ci][0];
            const float k1 = sW[l][co][ci][1];
            const float k2 = sW[l][co][ci][2];
            float r[8];
            #pragma unroll
            for (int w = 0; w < 8; w++) r[w] = inr[w];
            acc[0] += k1 * r[0] + k2 * r[1];
            #pragma unroll
            for (int w = 1; w < 7; w++)
                acc[w] += k0 * r[w - 1] + k1 * r[w] + k2 * r[w + 1];
            acc[7] += k0 * r[6] + k1 * r[7];
        }

        const float pa = sA[l];
        const float* selfr = cur + slab * 72 + co * 9;
        float* outr        = nxt + slab * 72 + co * 9;
        #pragma unroll
        for (int w = 0; w < 8; w++) {
            float y = acc[w];
            y = (y >= 0.f) ? y : pa * y;        // PReLU
            outr[w] = y + selfr[w];             // residual
        }
        __syncthreads();
        float* tmp = cur; cur = nxt; nxt = tmp;
    }
    // conv result in `cur`; sX holds original x

    // ---- we = expm1(relu(x - sigmoid(conv)) * (1-eye)); keep in registers ----
    float we[8];
    {
        const float* xr = &sX[slab][co][0];
        const float* cr = cur + slab * 72 + co * 9;
        float partial = 0.f;
        #pragma unroll
        for (int w = 0; w < 8; w++) {
            float sg = 1.f / (1.f + __expf(-cr[w]));
            float sp = fmaxf(xr[w] - sg, 0.f);
            if (hh == w) sp = 0.f;              // self mask
            float v = expm1f(sp);
            if (!pvalid) v = 0.f;
            we[w] = v;
            partial += v;
        }
        sPS[pp][hh][co] = partial;
    }
    __syncthreads();

    if (tid < 64) {
        const int th = tid >> 3, tc = tid & 7;
        float s = sPS[0][th][tc] + sPS[1][th][tc] + sPS[2][th][tc] + sPS[3][th][tc];
        sInv[th][tc] = 1.f / (s + EPS_F);
    }
    __syncthreads();

    // ---- scale + direct store: 8 contiguous floats at (b,co,i,hh, j*8) ----
    if (pvalid) {
        const float inv = sInv[hh][co];
        float* dst = out +
            ((size_t)((b * 8 + co) * 1024 + (i * 8 + hh)) * 1024 + (size_t)j * 8);
        float4 o0 = make_float4(we[0]*inv, we[1]*inv, we[2]*inv, we[3]*inv);
        float4 o1 = make_float4(we[4]*inv, we[5]*inv, we[6]*inv, we[7]*inv);
        *(float4*)dst       = o0;
        *(float4*)(dst + 4) = o1;
    }
}

extern "C" void kernel_launch(void* const* d_in, const int* in_sizes, int n_in,
                              void* d_out, int out_size) {
    const float* pw = (const float*)d_in[0];
    const float* cw = (const float*)d_in[1];
    const float* cb = (const float*)d_in[2];
    const float* pa = (const float*)d_in[3];
    // Zero background first (graph-capturable memset node); compute kernel
    // then overwrites only the nonzero near-diagonal blocks (~8 MB of 256 MB).
    cudaMemsetAsync(d_out, 0, (size_t)out_size * sizeof(float));
    sag_compute<<<1024, 256>>>(pw, cw, cb, pa, (float*)d_out);
}

// round 3
// speedup vs baseline: 1.6033x; 1.4492x over previous
#include <cuda_runtime.h>

#define NLAYERS 7
#define EPS_F 1e-5f

// Shapes (fixed by setup_inputs): bsz=8, C=8, QL=KL=128, A=8, cross_range=2
// pw / out: [64, 1024, 1024] f32;  conv_w: [7,8,8,1,3]; conv_b: [7,8]; prelu_a: [7]
//
// Single merged kernel, one CTA per (b, q):
//   - streams zeros to the 248 non-band float4-columns of its 256KB output
//     region up-front (each address written exactly once in the kernel),
//   - runs the 7-layer residual conv stack on the <=4 neighbor A*A blocks in
//     SMEM (float4 LDS, stride-68 padded rows),
//   - writes the normalized band values at the end.
// Zero is correct background: expm1(0)=0, 0/(sum+eps)=0.

__device__ __forceinline__ void stcs4(float* p, float4 v) {
    asm volatile("st.global.cs.v4.f32 [%0], {%1,%2,%3,%4};"
                 :: "l"(p), "f"(v.x), "f"(v.y), "f"(v.z), "f"(v.w) : "memory");
}

__global__ __launch_bounds__(256, 5)
void sag_merged(const float* __restrict__ pw,
                const float* __restrict__ conv_w,
                const float* __restrict__ conv_b,
                const float* __restrict__ prelu_a,
                float* __restrict__ out)
{
    __shared__ float4 sW4[NLAYERS][8][8];            // [l][ci][co] = (k0,k1,k2,_)
    __shared__ float  sB [NLAYERS][8];
    __shared__ float  sA [NLAYERS];
    __shared__ __align__(16) float sD0[32 * 68];     // ping  [slab]*68 + [ci]*8 + w
    __shared__ __align__(16) float sD1[32 * 68];     // pong
    __shared__ __align__(16) float sRes[4][8][8][8]; // x, later we   [pp][hh][co][w]
    __shared__ float  sPS[4][8][8];                  // partial row sums [pp][hh][co]
    __shared__ float  sInv[8][8];                    // 1/(rowsum+eps)   [hh][co]

    const int tid = threadIdx.x;
    const int b = blockIdx.x >> 7;            // batch
    const int i = blockIdx.x & 127;           // query index

    // ---- conv params -> SMEM (weights repacked [l][ci][co] as float4) ----
    for (int t = tid; t < NLAYERS * 64; t += 256) {
        const int l = t >> 6, rem = t & 63, wco = rem >> 3, wci = rem & 7;
        const float* src = conv_w + ((l * 8 + wco) * 8 + wci) * 3;
        sW4[l][wci][wco] = make_float4(src[0], src[1], src[2], 0.f);
    }
    if (tid < NLAYERS * 8) (&sB[0][0])[tid] = conv_b[tid];
    if (tid < NLAYERS)     sA[tid] = prelu_a[tid];

    // thread roles for compute: slab = pp*8 + hh, co = channel
    const int slab = tid >> 3;
    const int co   = tid & 7;
    const int pp   = slab >> 3;
    const int hh   = slab & 7;
    const int doff = (pp < 2) ? (pp - 2) : (pp - 1);  // {-2,-1,1,2}
    const int j    = i + doff;
    const bool pvalid = (j >= 0) && (j < 128);

    // ---- issue x loads first (latency hides under the zero-store loop) ----
    float4 v0 = make_float4(0.f, 0.f, 0.f, 0.f), v1 = v0;
    if (pvalid) {
        const float* src = pw +
            ((size_t)((b * 8 + co) * 1024 + (i * 8 + hh)) * 1024 + (size_t)j * 8);
        v0 = *(const float4*)src;
        v1 = *(const float4*)(src + 4);
    }

    // thread roles for stores: float4-column = tid, block column k = tid>>1
    const int kcol = tid >> 1;
    const int d    = kcol - i;
    int pi = -1;
    if      (d == -2) pi = 0;
    else if (d == -1) pi = 1;
    else if (d ==  1) pi = 2;
    else if (d ==  2) pi = 3;
    const size_t base = ((size_t)(b * 8) * 1024 + (size_t)i * 8) * 1024;

    // ---- zero-store phase: 64 rows x this thread's float4 column ----
    if (pi < 0) {
        const float4 z = make_float4(0.f, 0.f, 0.f, 0.f);
        float* p0 = out + base + (size_t)tid * 4;
        #pragma unroll 2
        for (int rc = 0; rc < 8; rc++) {
            float* pr = p0 + (size_t)rc * (1024 * 1024);
            #pragma unroll
            for (int rh = 0; rh < 8; rh++)
                stcs4(pr + rh * 1024, z);
        }
    }

    // ---- stash x (sRes doubles as x backup) and seed ping buffer ----
    {
        float* row = sD0 + slab * 68 + co * 8;
        *(float4*)row       = v0;
        *(float4*)(row + 4) = v1;
        *(float4*)&sRes[pp][hh][co][0] = v0;
        *(float4*)&sRes[pp][hh][co][4] = v1;
    }
    __syncthreads();

    // ---- 7-layer residual conv stack ----
    float* cur = sD0;
    float* nxt = sD1;
    #pragma unroll 1
    for (int l = 0; l < NLAYERS; l++) {
        const float bias = sB[l][co];
        float acc[8];
        #pragma unroll
        for (int w = 0; w < 8; w++) acc[w] = bias;

        #pragma unroll
        for (int ci = 0; ci < 8; ci++) {
            const float4 wv = sW4[l][ci][co];
            const float* inr = cur + slab * 68 + ci * 8;
            const float4 ra = *(const float4*)inr;
            const float4 rb = *(const float4*)(inr + 4);
            acc[0] += wv.y * ra.x + wv.z * ra.y;
            acc[1] += wv.x * ra.x + wv.y * ra.y + wv.z * ra.z;
            acc[2] += wv.x * ra.y + wv.y * ra.z + wv.z * ra.w;
            acc[3] += wv.x * ra.z + wv.y * ra.w + wv.z * rb.x;
            acc[4] += wv.x * ra.w + wv.y * rb.x + wv.z * rb.y;
            acc[5] += wv.x * rb.x + wv.y * rb.y + wv.z * rb.z;
            acc[6] += wv.x * rb.y + wv.y * rb.z + wv.z * rb.w;
            acc[7] += wv.x * rb.z + wv.y * rb.w;
        }

        const float pa = sA[l];
        const float* selfr = cur + slab * 68 + co * 8;
        const float4 s0 = *(const float4*)selfr;
        const float4 s1 = *(const float4*)(selfr + 4);
        float4 o0, o1;
        o0.x = ((acc[0] >= 0.f) ? acc[0] : pa * acc[0]) + s0.x;
        o0.y = ((acc[1] >= 0.f) ? acc[1] : pa * acc[1]) + s0.y;
        o0.z = ((acc[2] >= 0.f) ? acc[2] : pa * acc[2]) + s0.z;
        o0.w = ((acc[3] >= 0.f) ? acc[3] : pa * acc[3]) + s0.w;
        o1.x = ((acc[4] >= 0.f) ? acc[4] : pa * acc[4]) + s1.x;
        o1.y = ((acc[5] >= 0.f) ? acc[5] : pa * acc[5]) + s1.y;
        o1.z = ((acc[6] >= 0.f) ? acc[6] : pa * acc[6]) + s1.z;
        o1.w = ((acc[7] >= 0.f) ? acc[7] : pa * acc[7]) + s1.w;
        float* outr = nxt + slab * 68 + co * 8;
        *(float4*)outr       = o0;
        *(float4*)(outr + 4) = o1;
        __syncthreads();
        float* tmp = cur; cur = nxt; nxt = tmp;
    }

    // ---- we = expm1(relu(x - sigmoid(conv)) * (1-eye)); write back to sRes ----
    {
        const float* cr = cur + slab * 68 + co * 8;
        const float4 c0 = *(const float4*)cr;
        const float4 c1 = *(const float4*)(cr + 4);
        const float4 x0 = *(const float4*)&sRes[pp][hh][co][0];
        const float4 x1 = *(const float4*)&sRes[pp][hh][co][4];
        float cv[8] = {c0.x, c0.y, c0.z, c0.w, c1.x, c1.y, c1.z, c1.w};
        float xv[8] = {x0.x, x0.y, x0.z, x0.w, x1.x, x1.y, x1.z, x1.w};
        float we[8];
        float partial = 0.f;
        #pragma unroll
        for (int w = 0; w < 8; w++) {
            const float sg = 1.f / (1.f + __expf(-cv[w]));
            float sp = fmaxf(xv[w] - sg, 0.f);
            if (hh == w) sp = 0.f;              // self mask
            float v = expm1f(sp);
            if (!pvalid) v = 0.f;
            we[w] = v;
            partial += v;
        }
        *(float4*)&sRes[pp][hh][co][0] = make_float4(we[0], we[1], we[2], we[3]);
        *(float4*)&sRes[pp][hh][co][4] = make_float4(we[4], we[5], we[6], we[7]);
        sPS[pp][hh][co] = partial;
    }
    __syncthreads();

    if (tid < 64) {
        const int th = tid >> 3, tc = tid & 7;
        const float s = sPS[0][th][tc] + sPS[1][th][tc] + sPS[2][th][tc] + sPS[3][th][tc];
        sInv[th][tc] = 1.f / (s + EPS_F);
    }
    __syncthreads();

    // ---- band-store phase: the 8 band threads write their column ----
    if (pi >= 0) {
        const int w0 = (tid & 1) * 4;
        float* p0 = out + base + (size_t)tid * 4;
        #pragma unroll 1
        for (int rc = 0; rc < 8; rc++) {
            float* pr = p0 + (size_t)rc * (1024 * 1024);
            #pragma unroll
            for (int rh = 0; rh < 8; rh++) {
                const float4 r = *(const float4*)&sRes[pi][rh][rc][w0];
                const float inv = sInv[rh][rc];
                stcs4(pr + rh * 1024,
                      make_float4(r.x * inv, r.y * inv, r.z * inv, r.w * inv));
            }
        }
    }
}

extern "C" void kernel_launch(void* const* d_in, const int* in_sizes, int n_in,
                              void* d_out, int out_size) {
    const float* pw = (const float*)d_in[0];
    const float* cw = (const float*)d_in[1];
    const float* cb = (const float*)d_in[2];
    const float* pa = (const float*)d_in[3];
    sag_merged<<<1024, 256>>>(pw, cw, cb, pa, (float*)d_out);
}

// round 4
// speedup vs baseline: 1.6116x; 1.0052x over previous
#include <cuda_runtime.h>

#define NLAYERS 7
#define EPS_F 1e-5f

// Shapes (fixed by setup_inputs): bsz=8, C=8, QL=KL=128, A=8, cross_range=2
// pw / out: [64, 1024, 1024] f32;  conv_w: [7,8,8,1,3]; conv_b: [7,8]; prelu_a: [7]
//
// Single merged kernel, one CTA per (b, q):
//   - streams zeros to the 248 non-band float4-columns of its 256KB output
//     region up-front (each address written exactly once in the kernel),
//   - runs the 7-layer residual conv stack on the <=4 neighbor A*A blocks in
//     SMEM (float4 LDS, stride-68 padded rows),
//   - writes the normalized band values at the end.
// Zero is correct background: expm1(0)=0, 0/(sum+eps)=0.

__device__ __forceinline__ void stcs4(float* p, float4 v) {
    asm volatile("st.global.cs.v4.f32 [%0], {%1,%2,%3,%4};"
                 :: "l"(p), "f"(v.x), "f"(v.y), "f"(v.z), "f"(v.w) : "memory");
}

__global__ __launch_bounds__(256, 5)
void sag_merged(const float* __restrict__ pw,
                const float* __restrict__ conv_w,
                const float* __restrict__ conv_b,
                const float* __restrict__ prelu_a,
                float* __restrict__ out)
{
    __shared__ float4 sW4[NLAYERS][8][8];            // [l][ci][co] = (k0,k1,k2,_)
    __shared__ float  sB [NLAYERS][8];
    __shared__ float  sA [NLAYERS];
    __shared__ __align__(16) float sD0[32 * 68];     // ping  [slab]*68 + [ci]*8 + w
    __shared__ __align__(16) float sD1[32 * 68];     // pong
    __shared__ __align__(16) float sRes[4][8][8][8]; // x, later we   [pp][hh][co][w]
    __shared__ float  sPS[4][8][8];                  // partial row sums [pp][hh][co]
    __shared__ float  sInv[8][8];                    // 1/(rowsum+eps)   [hh][co]

    const int tid = threadIdx.x;
    const int b = blockIdx.x >> 7;            // batch
    const int i = blockIdx.x & 127;           // query index

    // ---- conv params -> SMEM (weights repacked [l][ci][co] as float4) ----
    for (int t = tid; t < NLAYERS * 64; t += 256) {
        const int l = t >> 6, rem = t & 63, wco = rem >> 3, wci = rem & 7;
        const float* src = conv_w + ((l * 8 + wco) * 8 + wci) * 3;
        sW4[l][wci][wco] = make_float4(src[0], src[1], src[2], 0.f);
    }
    if (tid < NLAYERS * 8) (&sB[0][0])[tid] = conv_b[tid];
    if (tid < NLAYERS)     sA[tid] = prelu_a[tid];

    // thread roles for compute: slab = pp*8 + hh, co = channel
    const int slab = tid >> 3;
    const int co   = tid & 7;
    const int pp   = slab >> 3;
    const int hh   = slab & 7;
    const int doff = (pp < 2) ? (pp - 2) : (pp - 1);  // {-2,-1,1,2}
    const int j    = i + doff;
    const bool pvalid = (j >= 0) && (j < 128);

    // ---- issue x loads first (latency hides under the zero-store loop) ----
    float4 v0 = make_float4(0.f, 0.f, 0.f, 0.f), v1 = v0;
    if (pvalid) {
        const float* src = pw +
            ((size_t)((b * 8 + co) * 1024 + (i * 8 + hh)) * 1024 + (size_t)j * 8);
        v0 = *(const float4*)src;
        v1 = *(const float4*)(src + 4);
    }

    // thread roles for stores: float4-column = tid, block column k = tid>>1
    const int kcol = tid >> 1;
    const int d    = kcol - i;
    int pi = -1;
    if      (d == -2) pi = 0;
    else if (d == -1) pi = 1;
    else if (d ==  1) pi = 2;
    else if (d ==  2) pi = 3;
    const size_t base = ((size_t)(b * 8) * 1024 + (size_t)i * 8) * 1024;

    // ---- zero-store phase: 64 rows x this thread's float4 column ----
    if (pi < 0) {
        const float4 z = make_float4(0.f, 0.f, 0.f, 0.f);
        float* p0 = out + base + (size_t)tid * 4;
        #pragma unroll 2
        for (int rc = 0; rc < 8; rc++) {
            float* pr = p0 + (size_t)rc * (1024 * 1024);
            #pragma unroll
            for (int rh = 0; rh < 8; rh++)
                stcs4(pr + rh * 1024, z);
        }
    }

    // ---- stash x (sRes doubles as x backup) and seed ping buffer ----
    {
        float* row = sD0 + slab * 68 + co * 8;
        *(float4*)row       = v0;
        *(float4*)(row + 4) = v1;
        *(float4*)&sRes[pp][hh][co][0] = v0;
        *(float4*)&sRes[pp][hh][co][4] = v1;
    }
    __syncthreads();

    // ---- 7-layer residual conv stack ----
    float* cur = sD0;
    float* nxt = sD1;
    #pragma unroll 1
    for (int l = 0; l < NLAYERS; l++) {
        const float bias = sB[l][co];
        float acc[8];
        #pragma unroll
        for (int w = 0; w < 8; w++) acc[w] = bias;

        #pragma unroll
        for (int ci = 0; ci < 8; ci++) {
            const float4 wv = sW4[l][ci][co];
            const float* inr = cur + slab * 68 + ci * 8;
            const float4 ra = *(const float4*)inr;
            const float4 rb = *(const float4*)(inr + 4);
            acc[0] += wv.y * ra.x + wv.z * ra.y;
            acc[1] += wv.x * ra.x + wv.y * ra.y + wv.z * ra.z;
            acc[2] += wv.x * ra.y + wv.y * ra.z + wv.z * ra.w;
            acc[3] += wv.x * ra.z + wv.y * ra.w + wv.z * rb.x;
            acc[4] += wv.x * ra.w + wv.y * rb.x + wv.z * rb.y;
            acc[5] += wv.x * rb.x + wv.y * rb.y + wv.z * rb.z;
            acc[6] += wv.x * rb.y + wv.y * rb.z + wv.z * rb.w;
            acc[7] += wv.x * rb.z + wv.y * rb.w;
        }

        const float pa = sA[l];
        const float* selfr = cur + slab * 68 + co * 8;
        const float4 s0 = *(const float4*)selfr;
        const float4 s1 = *(const float4*)(selfr + 4);
        float4 o0, o1;
        o0.x = ((acc[0] >= 0.f) ? acc[0] : pa * acc[0]) + s0.x;
        o0.y = ((acc[1] >= 0.f) ? acc[1] : pa * acc[1]) + s0.y;
        o0.z = ((acc[2] >= 0.f) ? acc[2] : pa * acc[2]) + s0.z;
        o0.w = ((acc[3] >= 0.f) ? acc[3] : pa * acc[3]) + s0.w;
        o1.x = ((acc[4] >= 0.f) ? acc[4] : pa * acc[4]) + s1.x;
        o1.y = ((acc[5] >= 0.f) ? acc[5] : pa * acc[5]) + s1.y;
        o1.z = ((acc[6] >= 0.f) ? acc[6] : pa * acc[6]) + s1.z;
        o1.w = ((acc[7] >= 0.f) ? acc[7] : pa * acc[7]) + s1.w;
        float* outr = nxt + slab * 68 + co * 8;
        *(float4*)outr       = o0;
        *(float4*)(outr + 4) = o1;
        __syncthreads();
        float* tmp = cur; cur = nxt; nxt = tmp;
    }

    // ---- we = expm1(relu(x - sigmoid(conv)) * (1-eye)); write back to sRes ----
    {
        const float* cr = cur + slab * 68 + co * 8;
        const float4 c0 = *(const float4*)cr;
        const float4 c1 = *(const float4*)(cr + 4);
        const float4 x0 = *(const float4*)&sRes[pp][hh][co][0];
        const float4 x1 = *(const float4*)&sRes[pp][hh][co][4];
        float cv[8] = {c0.x, c0.y, c0.z, c0.w, c1.x, c1.y, c1.z, c1.w};
        float xv[8] = {x0.x, x0.y, x0.z, x0.w, x1.x, x1.y, x1.z, x1.w};
        float we[8];
        float partial = 0.f;
        #pragma unroll
        for (int w = 0; w < 8; w++) {
            const float sg = 1.f / (1.f + __expf(-cv[w]));
            float sp = fmaxf(xv[w] - sg, 0.f);
            if (hh == w) sp = 0.f;              // self mask
            float v = expm1f(sp);
            if (!pvalid) v = 0.f;
            we[w] = v;
            partial += v;
        }
        *(float4*)&sRes[pp][hh][co][0] = make_float4(we[0], we[1], we[2], we[3]);
        *(float4*)&sRes[pp][hh][co][4] = make_float4(we[4], we[5], we[6], we[7]);
        sPS[pp][hh][co] = partial;
    }
    __syncthreads();

    if (tid < 64) {
        const int th = tid >> 3, tc = tid & 7;
        const float s = sPS[0][th][tc] + sPS[1][th][tc] + sPS[2][th][tc] + sPS[3][th][tc];
        sInv[th][tc] = 1.f / (s + EPS_F);
    }
    __syncthreads();

    // ---- band-store phase: the 8 band threads write their column ----
    if (pi >= 0) {
        const int w0 = (tid & 1) * 4;
        float* p0 = out + base + (size_t)tid * 4;
        #pragma unroll 1
        for (int rc = 0; rc < 8; rc++) {
            float* pr = p0 + (size_t)rc * (1024 * 1024);
            #pragma unroll
            for (int rh = 0; rh < 8; rh++) {
                const float4 r = *(const float4*)&sRes[pi][rh][rc][w0];
                const float inv = sInv[rh][rc];
                stcs4(pr + rh * 1024,
                      make_float4(r.x * inv, r.y * inv, r.z * inv, r.w * inv));
            }
        }
    }
}

extern "C" void kernel_launch(void* const* d_in, const int* in_sizes, int n_in,
                              void* d_out, int out_size) {
    const float* pw = (const float*)d_in[0];
    const float* cw = (const float*)d_in[1];
    const float* cb = (const float*)d_in[2];
    const float* pa = (const float*)d_in[3];
    sag_merged<<<1024, 256>>>(pw, cw, cb, pa, (float*)d_out);
}